// round 6
// baseline (speedup 1.0000x reference)
#include <cuda_runtime.h>
#include <cuda_fp16.h>
#include <cstdint>

#define D 128
#define MAX_NODES 100032
#define MAX_EDGES 3200000
#define CHUNK 1024
#define MAX_CHUNKS 1024

// ---- device scratch (static globals; allocation-free) ----
// h stored in fp16: 128 halves = 256B per row = 16 x uint4.
__device__ uint4 g_h[(size_t)MAX_NODES * 16];          // 25.6 MB
__device__ int2  g_csr[MAX_EDGES];                     // 25.6 MB (col, w-bits)
__device__ int   g_count[MAX_NODES];                   // starts 0; re-zeroed by apply
__device__ int   g_start[MAX_NODES + 1];
__device__ int   g_cursor[MAX_NODES];
__device__ int   g_chunk_sum[MAX_CHUNKS];
__device__ int   g_chunk_off[MAX_CHUNKS];

// ---------------------------------------------------------------------------
// GEMM body: h[gr][:] = x[gr][:] @ W^T, rows [row_off + tile*128, +128).
// 256 threads, 8x8 register tile per thread, fp16 output.
// ---------------------------------------------------------------------------
__device__ __forceinline__ void gemm_body(const float* __restrict__ x,
                                          const float* __restrict__ W,
                                          int tile, int row_off, int n_rows) {
    __shared__ float xs[8][132];
    __shared__ float ws[8][132];

    const int tid = threadIdx.x;
    const int block_row = row_off + tile * 128;
    const int ty = tid >> 4;
    const int tx = tid & 15;
    const int r_load = tid >> 1;
    const int k_half = (tid & 1) * 4;

    float acc[8][8];
#pragma unroll
    for (int i = 0; i < 8; i++)
#pragma unroll
        for (int j = 0; j < 8; j++) acc[i][j] = 0.f;

    for (int k0 = 0; k0 < D; k0 += 8) {
        {
            const int gr = block_row + r_load;
            float4 v = make_float4(0.f, 0.f, 0.f, 0.f);
            if (gr < n_rows)
                v = *(const float4*)(x + (size_t)gr * D + k0 + k_half);
            xs[k_half + 0][r_load] = v.x;
            xs[k_half + 1][r_load] = v.y;
            xs[k_half + 2][r_load] = v.z;
            xs[k_half + 3][r_load] = v.w;
        }
        {
            const float4 v = *(const float4*)(W + (size_t)r_load * D + k0 + k_half);
            ws[k_half + 0][r_load] = v.x;
            ws[k_half + 1][r_load] = v.y;
            ws[k_half + 2][r_load] = v.z;
            ws[k_half + 3][r_load] = v.w;
        }
        __syncthreads();

#pragma unroll
        for (int kk = 0; kk < 8; kk++) {
            float a[8], b[8];
            *(float4*)&a[0] = *(const float4*)&xs[kk][ty * 8];
            *(float4*)&a[4] = *(const float4*)&xs[kk][ty * 8 + 4];
            *(float4*)&b[0] = *(const float4*)&ws[kk][tx * 8];
            *(float4*)&b[4] = *(const float4*)&ws[kk][tx * 8 + 4];
#pragma unroll
            for (int i = 0; i < 8; i++)
#pragma unroll
                for (int j = 0; j < 8; j++)
                    acc[i][j] += a[i] * b[j];
        }
        __syncthreads();
    }

#pragma unroll
    for (int i = 0; i < 8; i++) {
        const int gr = block_row + ty * 8 + i;
        if (gr < n_rows) {
            __half2 p0 = __floats2half2_rn(acc[i][0], acc[i][1]);
            __half2 p1 = __floats2half2_rn(acc[i][2], acc[i][3]);
            __half2 p2 = __floats2half2_rn(acc[i][4], acc[i][5]);
            __half2 p3 = __floats2half2_rn(acc[i][6], acc[i][7]);
            uint4 pk;
            pk.x = *reinterpret_cast<unsigned*>(&p0);
            pk.y = *reinterpret_cast<unsigned*>(&p1);
            pk.z = *reinterpret_cast<unsigned*>(&p2);
            pk.w = *reinterpret_cast<unsigned*>(&p3);
            g_h[(size_t)gr * 16 + tx] = pk;
        }
    }
}

// ---------------------------------------------------------------------------
// fat1: hist (blocks [0, hist_blocks)) + GEMM first half (remaining blocks).
// ---------------------------------------------------------------------------
__global__ __launch_bounds__(256) void fat1_kernel(const float* __restrict__ x,
                                                   const float* __restrict__ W,
                                                   const int* __restrict__ edges,
                                                   int n_edges, int n_nodes,
                                                   int hist_blocks) {
    if ((int)blockIdx.x < hist_blocks) {
        const int nq = n_edges >> 2;
        const int stride = hist_blocks * blockDim.x;
        for (int q = blockIdx.x * blockDim.x + threadIdx.x; q < nq; q += stride) {
            const int4 r = ((const int4*)edges)[q];
            if ((unsigned)r.x < (unsigned)n_nodes) atomicAdd(&g_count[r.x], 1);
            if ((unsigned)r.y < (unsigned)n_nodes) atomicAdd(&g_count[r.y], 1);
            if ((unsigned)r.z < (unsigned)n_nodes) atomicAdd(&g_count[r.z], 1);
            if ((unsigned)r.w < (unsigned)n_nodes) atomicAdd(&g_count[r.w], 1);
        }
        if (blockIdx.x == 0 && (int)threadIdx.x < (n_edges & 3)) {
            int e = (nq << 2) + threadIdx.x;
            int row = edges[e];
            if ((unsigned)row < (unsigned)n_nodes) atomicAdd(&g_count[row], 1);
        }
    } else {
        gemm_body(x, W, blockIdx.x - hist_blocks, 0, n_nodes);
    }
}

// ---------------------------------------------------------------------------
// Scan chain (3-level, all grid-parallel)
// ---------------------------------------------------------------------------
__global__ __launch_bounds__(256) void chunk_reduce_kernel(int n_nodes) {
    const int base = blockIdx.x * CHUNK;
    const int tid = threadIdx.x;
    int sum = 0;
#pragma unroll
    for (int j = 0; j < CHUNK / 256; j++) {
        int i = base + j * 256 + tid;
        if (i < n_nodes) sum += g_count[i];
    }
    for (int off = 16; off > 0; off >>= 1)
        sum += __shfl_down_sync(0xffffffffu, sum, off);
    __shared__ int ws[8];
    if ((tid & 31) == 0) ws[tid >> 5] = sum;
    __syncthreads();
    if (tid < 8) {
        int v = ws[tid];
        for (int off = 4; off > 0; off >>= 1)
            v += __shfl_down_sync(0xffu, v, off);
        if (tid == 0) g_chunk_sum[blockIdx.x] = v;
    }
}

__global__ __launch_bounds__(1024) void chunk_scan_kernel(int n_chunks, int n_nodes,
                                                          int n_edges) {
    const int tid = threadIdx.x;
    __shared__ int s[MAX_CHUNKS];
    int v = (tid < n_chunks) ? g_chunk_sum[tid] : 0;
    s[tid] = v;
    __syncthreads();
#pragma unroll
    for (int off = 1; off < MAX_CHUNKS; off <<= 1) {
        int t = (tid >= off) ? s[tid - off] : 0;
        __syncthreads();
        s[tid] += t;
        __syncthreads();
    }
    if (tid < n_chunks) g_chunk_off[tid] = s[tid] - v;
    if (tid == 0) g_start[n_nodes] = n_edges;
}

// Also re-zeros g_count so the next pipeline run (graph replay) starts clean.
__global__ __launch_bounds__(1024) void chunk_apply_kernel(int n_nodes) {
    const int tid = threadIdx.x;
    const int i = blockIdx.x * CHUNK + tid;
    __shared__ int s[CHUNK];
    int v = 0;
    if (i < n_nodes) {
        v = g_count[i];
        g_count[i] = 0;
    }
    s[tid] = v;
    __syncthreads();
#pragma unroll
    for (int off = 1; off < CHUNK; off <<= 1) {
        int t = (tid >= off) ? s[tid - off] : 0;
        __syncthreads();
        s[tid] += t;
        __syncthreads();
    }
    if (i < n_nodes) {
        int start = g_chunk_off[blockIdx.x] + s[tid] - v;
        g_start[i] = start;
        g_cursor[i] = start;
    }
}

// ---------------------------------------------------------------------------
// fat2: fill (blocks [0, fill_blocks)) + GEMM second half (remaining blocks).
// ---------------------------------------------------------------------------
__global__ __launch_bounds__(256) void fat2_kernel(const float* __restrict__ x,
                                                   const float* __restrict__ W,
                                                   const int* __restrict__ edges,
                                                   const float* __restrict__ wts,
                                                   int n_edges, int n_nodes,
                                                   int fill_blocks, int row_off) {
    if ((int)blockIdx.x < fill_blocks) {
        const int nq = n_edges >> 2;
        const int stride = fill_blocks * blockDim.x;
        for (int q = blockIdx.x * blockDim.x + threadIdx.x; q < nq; q += stride) {
            const int4 r = ((const int4*)edges)[q];
            const int4 c = ((const int4*)(edges + n_edges))[q];
            const float4 w4 = ((const float4*)wts)[q];
            if ((unsigned)r.x < (unsigned)n_nodes && (unsigned)c.x < (unsigned)n_nodes) {
                int pos = atomicAdd(&g_cursor[r.x], 1);
                g_csr[pos] = make_int2(c.x, __float_as_int(w4.x));
            }
            if ((unsigned)r.y < (unsigned)n_nodes && (unsigned)c.y < (unsigned)n_nodes) {
                int pos = atomicAdd(&g_cursor[r.y], 1);
                g_csr[pos] = make_int2(c.y, __float_as_int(w4.y));
            }
            if ((unsigned)r.z < (unsigned)n_nodes && (unsigned)c.z < (unsigned)n_nodes) {
                int pos = atomicAdd(&g_cursor[r.z], 1);
                g_csr[pos] = make_int2(c.z, __float_as_int(w4.z));
            }
            if ((unsigned)r.w < (unsigned)n_nodes && (unsigned)c.w < (unsigned)n_nodes) {
                int pos = atomicAdd(&g_cursor[r.w], 1);
                g_csr[pos] = make_int2(c.w, __float_as_int(w4.w));
            }
        }
        if (blockIdx.x == 0 && (int)threadIdx.x < (n_edges & 3)) {
            int e = (nq << 2) + threadIdx.x;
            int row = edges[e];
            int col = edges[n_edges + e];
            if ((unsigned)row < (unsigned)n_nodes && (unsigned)col < (unsigned)n_nodes) {
                int pos = atomicAdd(&g_cursor[row], 1);
                g_csr[pos] = make_int2(col, __float_as_int(wts[e]));
            }
        }
    } else {
        gemm_body(x, W, blockIdx.x - fill_blocks, row_off, n_nodes);
    }
}

// ---------------------------------------------------------------------------
// Aggregation: one warp per output node, no atomics, fp16 gather, unroll-2.
// lane l owns halves [4l, 4l+4) of the 128-wide row (uint2 = 8B per lane).
// ---------------------------------------------------------------------------
__global__ __launch_bounds__(256) void agg_kernel(float* __restrict__ out, int n_nodes) {
    const int lane = threadIdx.x & 31;
    const int node = (blockIdx.x * blockDim.x + threadIdx.x) >> 5;
    if (node >= n_nodes) return;

    const int s = g_start[node];
    const int e = g_start[node + 1];

    float4 acc0 = make_float4(0.f, 0.f, 0.f, 0.f);
    float4 acc1 = make_float4(0.f, 0.f, 0.f, 0.f);

    int i = s;
    for (; i + 2 <= e; i += 2) {
        const int2 cw0 = g_csr[i];
        const int2 cw1 = g_csr[i + 1];
        const uint2 p0 = ((const uint2*)(g_h + (size_t)cw0.x * 16))[lane];
        const uint2 p1 = ((const uint2*)(g_h + (size_t)cw1.x * 16))[lane];
        const float w0 = __int_as_float(cw0.y);
        const float w1 = __int_as_float(cw1.y);

        float2 a0 = __half22float2(*reinterpret_cast<const __half2*>(&p0.x));
        float2 b0 = __half22float2(*reinterpret_cast<const __half2*>(&p0.y));
        acc0.x += w0 * a0.x; acc0.y += w0 * a0.y;
        acc0.z += w0 * b0.x; acc0.w += w0 * b0.y;

        float2 a1 = __half22float2(*reinterpret_cast<const __half2*>(&p1.x));
        float2 b1 = __half22float2(*reinterpret_cast<const __half2*>(&p1.y));
        acc1.x += w1 * a1.x; acc1.y += w1 * a1.y;
        acc1.z += w1 * b1.x; acc1.w += w1 * b1.y;
    }
    if (i < e) {
        const int2 cw = g_csr[i];
        const uint2 p = ((const uint2*)(g_h + (size_t)cw.x * 16))[lane];
        const float wt = __int_as_float(cw.y);
        float2 a = __half22float2(*reinterpret_cast<const __half2*>(&p.x));
        float2 b = __half22float2(*reinterpret_cast<const __half2*>(&p.y));
        acc0.x += wt * a.x; acc0.y += wt * a.y;
        acc0.z += wt * b.x; acc0.w += wt * b.y;
    }

    acc0.x += acc1.x; acc0.y += acc1.y; acc0.z += acc1.z; acc0.w += acc1.w;
    ((float4*)(out + (size_t)node * D))[lane] = acc0;
}

// ---------------------------------------------------------------------------
// Launch
// ---------------------------------------------------------------------------
extern "C" void kernel_launch(void* const* d_in, const int* in_sizes, int n_in,
                              void* d_out, int out_size) {
    const float* node_emb    = (const float*)d_in[0];
    const int*   edges       = (const int*)d_in[1];
    const float* edge_weight = (const float*)d_in[2];
    const float* W           = (const float*)d_in[3];
    float*       out         = (float*)d_out;

    const int n_nodes = in_sizes[0] / D;
    const int n_edges = in_sizes[1] / 2;
    const int n_chunks = (n_nodes + CHUNK - 1) / CHUNK;

    const int total_tiles = (n_nodes + 127) / 128;
    const int tiles1 = total_tiles / 2;           // GEMM first half
    const int tiles2 = total_tiles - tiles1;      // GEMM second half
    const int row_off2 = tiles1 * 128;

    const int HIST_BLOCKS = 1024;
    const int FILL_BLOCKS = 2048;

    // Phase 1: hist + GEMM(rows 0..half) fused
    fat1_kernel<<<HIST_BLOCKS + tiles1, 256, 0, 0>>>(node_emb, W, edges,
                                                     n_edges, n_nodes, HIST_BLOCKS);
    // Scan chain
    chunk_reduce_kernel<<<n_chunks, 256, 0, 0>>>(n_nodes);
    chunk_scan_kernel<<<1, MAX_CHUNKS, 0, 0>>>(n_chunks, n_nodes, n_edges);
    chunk_apply_kernel<<<n_chunks, CHUNK, 0, 0>>>(n_nodes);

    // Phase 2: fill + GEMM(rows half..N) fused
    fat2_kernel<<<FILL_BLOCKS + tiles2, 256, 0, 0>>>(node_emb, W, edges, edge_weight,
                                                     n_edges, n_nodes, FILL_BLOCKS,
                                                     row_off2);

    // Atomic-free aggregation; writes every output row
    const int agg_threads = n_nodes * 32;
    agg_kernel<<<(agg_threads + 255) / 256, 256, 0, 0>>>(out, n_nodes);
}

// round 8
// speedup vs baseline: 1.4029x; 1.4029x over previous
#include <cuda_runtime.h>
#include <cuda_fp16.h>
#include <mma.h>
#include <cstdint>

using namespace nvcuda;

#define D 128
#define MAX_NODES 100032
#define MAX_EDGES 3200000
#define CHUNK 1024
#define MAX_CHUNKS 1024

// ---- device scratch (static globals; allocation-free) ----
__device__ uint4 g_h[(size_t)MAX_NODES * 16];   // 25.6 MB, h in fp16 (128 halfs/row)
__device__ int2  g_csr[MAX_EDGES];              // 25.6 MB (col, w-bits)
__device__ int   g_count[MAX_NODES];            // starts 0; re-zeroed by apply
__device__ int   g_start[MAX_NODES + 1];
__device__ int   g_cursor[MAX_NODES];
__device__ int   g_chunk_sum[MAX_CHUNKS];
__device__ int   g_chunk_off[MAX_CHUNKS];

// ---------------------------------------------------------------------------
// Tensor-core GEMM: h = x @ W^T, fp16 inputs (converted in-flight), fp32 acc,
// fp16 output. Block tile 128x128 (full N), 8 warps: 4(M) x 2(N), each warp
// 32x64 = 2x4 wmma 16x16x16 fragments. W held entirely in smem.
// Epilogue stages fragments in smem with ld=20 floats (80B, multiple of 16B
// as wmma requires; ld=17 was the R7 corruption bug).
// ---------------------------------------------------------------------------
__global__ __launch_bounds__(256) void gemm_tc_kernel(const float* __restrict__ x,
                                                      const float* __restrict__ W,
                                                      int n_rows) {
    __shared__ __align__(32) __half ws[128][136];   // ws[n][k] = W[n][k]
    __shared__ __align__(32) __half xs[128][24];    // xs[m][k-chunk of 16]

    const int tid = threadIdx.x;
    const int warp = tid >> 5;
    const int lane = tid & 31;
    const int block_row = blockIdx.x * 128;
    const int wm = warp & 3;   // M group: rows wm*32 .. +32
    const int wn = warp >> 2;  // N group: cols wn*64 .. +64

    // Load + convert all of W (128x128 f32 -> fp16 smem)
    for (int q = tid; q < 128 * 32; q += 256) {
        const int r = q >> 5;
        const int c4 = q & 31;
        const float4 v = ((const float4*)(W + (size_t)r * D))[c4];
        const __half2 h0 = __floats2half2_rn(v.x, v.y);
        const __half2 h1 = __floats2half2_rn(v.z, v.w);
        uint2 pk;
        pk.x = *reinterpret_cast<const unsigned*>(&h0);
        pk.y = *reinterpret_cast<const unsigned*>(&h1);
        *(uint2*)&ws[r][c4 * 4] = pk;
    }

    wmma::fragment<wmma::accumulator, 16, 16, 16, float> c[2][4];
#pragma unroll
    for (int mi = 0; mi < 2; mi++)
#pragma unroll
        for (int ni = 0; ni < 4; ni++)
            wmma::fill_fragment(c[mi][ni], 0.f);

    for (int kt = 0; kt < 8; kt++) {
        const int k0 = kt * 16;
        __syncthreads();
        // load x tile: 128 rows x 16 halfs; thread t -> row t/2, 8-float seg t%2
        {
            const int row = tid >> 1;
            const int seg = (tid & 1) * 8;
            float4 v0 = make_float4(0.f, 0.f, 0.f, 0.f);
            float4 v1 = v0;
            const int gr = block_row + row;
            if (gr < n_rows) {
                const float* p = x + (size_t)gr * D + k0 + seg;
                v0 = *(const float4*)p;
                v1 = *(const float4*)(p + 4);
            }
            const __half2 a0 = __floats2half2_rn(v0.x, v0.y);
            const __half2 a1 = __floats2half2_rn(v0.z, v0.w);
            const __half2 a2 = __floats2half2_rn(v1.x, v1.y);
            const __half2 a3 = __floats2half2_rn(v1.z, v1.w);
            uint4 pk;
            pk.x = *reinterpret_cast<const unsigned*>(&a0);
            pk.y = *reinterpret_cast<const unsigned*>(&a1);
            pk.z = *reinterpret_cast<const unsigned*>(&a2);
            pk.w = *reinterpret_cast<const unsigned*>(&a3);
            *(uint4*)&xs[row][seg] = pk;
        }
        __syncthreads();

        wmma::fragment<wmma::matrix_a, 16, 16, 16, __half, wmma::row_major> a[2];
        wmma::fragment<wmma::matrix_b, 16, 16, 16, __half, wmma::col_major> b[4];
#pragma unroll
        for (int mi = 0; mi < 2; mi++)
            wmma::load_matrix_sync(a[mi], &xs[wm * 32 + mi * 16][0], 24);
#pragma unroll
        for (int ni = 0; ni < 4; ni++)
            wmma::load_matrix_sync(b[ni], &ws[wn * 64 + ni * 16][k0], 136);
#pragma unroll
        for (int mi = 0; mi < 2; mi++)
#pragma unroll
            for (int ni = 0; ni < 4; ni++)
                wmma::mma_sync(c[mi][ni], a[mi], b[ni], c[mi][ni]);
    }

    // Epilogue: per-warp 16x20-float stage (ld=20 -> 80B, legal wmma ldm),
    // convert to fp16, write to g_h.
    __syncthreads();  // all warps done reading ws/xs
    float* stage = (float*)ws + warp * 320;  // 16x20 floats per warp
    __half* hbase = (__half*)g_h;
#pragma unroll
    for (int mi = 0; mi < 2; mi++) {
#pragma unroll
        for (int ni = 0; ni < 4; ni++) {
            wmma::store_matrix_sync(stage, c[mi][ni], 20, wmma::mem_row_major);
            __syncwarp();
            const int r = lane >> 1;
            const int c8 = (lane & 1) * 8;
            const float* sp = stage + r * 20 + c8;
            const __half2 h0 = __floats2half2_rn(sp[0], sp[1]);
            const __half2 h1 = __floats2half2_rn(sp[2], sp[3]);
            const __half2 h2 = __floats2half2_rn(sp[4], sp[5]);
            const __half2 h3 = __floats2half2_rn(sp[6], sp[7]);
            uint4 pk;
            pk.x = *reinterpret_cast<const unsigned*>(&h0);
            pk.y = *reinterpret_cast<const unsigned*>(&h1);
            pk.z = *reinterpret_cast<const unsigned*>(&h2);
            pk.w = *reinterpret_cast<const unsigned*>(&h3);
            const int gr = block_row + wm * 32 + mi * 16 + r;
            const int col = wn * 64 + ni * 16 + c8;
            if (gr < n_rows)
                *(uint4*)(hbase + (size_t)gr * D + col) = pk;
            __syncwarp();
        }
    }
}

// ---------------------------------------------------------------------------
// hist: per-destination-row degree count (int4-vectorized edge reads)
// ---------------------------------------------------------------------------
__global__ __launch_bounds__(256) void hist_kernel(const int* __restrict__ edges,
                                                   int n_edges, int n_nodes) {
    const int nq = n_edges >> 2;
    const int q = blockIdx.x * blockDim.x + threadIdx.x;
    if (q < nq) {
        const int4 r = ((const int4*)edges)[q];
        if ((unsigned)r.x < (unsigned)n_nodes) atomicAdd(&g_count[r.x], 1);
        if ((unsigned)r.y < (unsigned)n_nodes) atomicAdd(&g_count[r.y], 1);
        if ((unsigned)r.z < (unsigned)n_nodes) atomicAdd(&g_count[r.z], 1);
        if ((unsigned)r.w < (unsigned)n_nodes) atomicAdd(&g_count[r.w], 1);
    }
    if (blockIdx.x == 0 && (int)threadIdx.x < (n_edges & 3)) {
        int e = (nq << 2) + threadIdx.x;
        int row = edges[e];
        if ((unsigned)row < (unsigned)n_nodes) atomicAdd(&g_count[row], 1);
    }
}

// ---------------------------------------------------------------------------
// Scan chain (3-level)
// ---------------------------------------------------------------------------
__global__ __launch_bounds__(256) void chunk_reduce_kernel(int n_nodes) {
    const int base = blockIdx.x * CHUNK;
    const int tid = threadIdx.x;
    int sum = 0;
#pragma unroll
    for (int j = 0; j < CHUNK / 256; j++) {
        int i = base + j * 256 + tid;
        if (i < n_nodes) sum += g_count[i];
    }
    for (int off = 16; off > 0; off >>= 1)
        sum += __shfl_down_sync(0xffffffffu, sum, off);
    __shared__ int ws[8];
    if ((tid & 31) == 0) ws[tid >> 5] = sum;
    __syncthreads();
    if (tid < 8) {
        int v = ws[tid];
        for (int off = 4; off > 0; off >>= 1)
            v += __shfl_down_sync(0xffu, v, off);
        if (tid == 0) g_chunk_sum[blockIdx.x] = v;
    }
}

__global__ __launch_bounds__(1024) void chunk_scan_kernel(int n_chunks, int n_nodes,
                                                          int n_edges) {
    const int tid = threadIdx.x;
    __shared__ int s[MAX_CHUNKS];
    int v = (tid < n_chunks) ? g_chunk_sum[tid] : 0;
    s[tid] = v;
    __syncthreads();
#pragma unroll
    for (int off = 1; off < MAX_CHUNKS; off <<= 1) {
        int t = (tid >= off) ? s[tid - off] : 0;
        __syncthreads();
        s[tid] += t;
        __syncthreads();
    }
    if (tid < n_chunks) g_chunk_off[tid] = s[tid] - v;
    if (tid == 0) g_start[n_nodes] = n_edges;
}

// Also re-zeros g_count for the next graph replay.
__global__ __launch_bounds__(1024) void chunk_apply_kernel(int n_nodes) {
    const int tid = threadIdx.x;
    const int i = blockIdx.x * CHUNK + tid;
    __shared__ int s[CHUNK];
    int v = 0;
    if (i < n_nodes) {
        v = g_count[i];
        g_count[i] = 0;
    }
    s[tid] = v;
    __syncthreads();
#pragma unroll
    for (int off = 1; off < CHUNK; off <<= 1) {
        int t = (tid >= off) ? s[tid - off] : 0;
        __syncthreads();
        s[tid] += t;
        __syncthreads();
    }
    if (i < n_nodes) {
        int start = g_chunk_off[blockIdx.x] + s[tid] - v;
        g_start[i] = start;
        g_cursor[i] = start;
    }
}

// ---------------------------------------------------------------------------
// fill: scatter (col, w) into CSR slots
// ---------------------------------------------------------------------------
__global__ __launch_bounds__(256) void fill_kernel(const int* __restrict__ edges,
                                                   const float* __restrict__ wts,
                                                   int n_edges, int n_nodes) {
    const int nq = n_edges >> 2;
    const int q = blockIdx.x * blockDim.x + threadIdx.x;
    if (q < nq) {
        const int4 r = ((const int4*)edges)[q];
        const int4 c = ((const int4*)(edges + n_edges))[q];
        const float4 w4 = ((const float4*)wts)[q];
        if ((unsigned)r.x < (unsigned)n_nodes && (unsigned)c.x < (unsigned)n_nodes) {
            int pos = atomicAdd(&g_cursor[r.x], 1);
            g_csr[pos] = make_int2(c.x, __float_as_int(w4.x));
        }
        if ((unsigned)r.y < (unsigned)n_nodes && (unsigned)c.y < (unsigned)n_nodes) {
            int pos = atomicAdd(&g_cursor[r.y], 1);
            g_csr[pos] = make_int2(c.y, __float_as_int(w4.y));
        }
        if ((unsigned)r.z < (unsigned)n_nodes && (unsigned)c.z < (unsigned)n_nodes) {
            int pos = atomicAdd(&g_cursor[r.z], 1);
            g_csr[pos] = make_int2(c.z, __float_as_int(w4.z));
        }
        if ((unsigned)r.w < (unsigned)n_nodes && (unsigned)c.w < (unsigned)n_nodes) {
            int pos = atomicAdd(&g_cursor[r.w], 1);
            g_csr[pos] = make_int2(c.w, __float_as_int(w4.w));
        }
    }
    if (blockIdx.x == 0 && (int)threadIdx.x < (n_edges & 3)) {
        int e = (nq << 2) + threadIdx.x;
        int row = edges[e];
        int col = edges[n_edges + e];
        if ((unsigned)row < (unsigned)n_nodes && (unsigned)col < (unsigned)n_nodes) {
            int pos = atomicAdd(&g_cursor[row], 1);
            g_csr[pos] = make_int2(col, __float_as_int(wts[e]));
        }
    }
}

// ---------------------------------------------------------------------------
// Aggregation: one warp per node. CSR entries batch-loaded 32-at-a-time
// (coalesced, lane-parallel) and distributed via shfl -> no per-edge
// dependent broadcast load. Inner loop unrolled x4, 2 accumulators.
// ---------------------------------------------------------------------------
__global__ __launch_bounds__(256) void agg_kernel(float* __restrict__ out, int n_nodes) {
    const int lane = threadIdx.x & 31;
    const int node = (blockIdx.x * blockDim.x + threadIdx.x) >> 5;
    if (node >= n_nodes) return;

    const int s = g_start[node];
    const int e = g_start[node + 1];

    float4 acc0 = make_float4(0.f, 0.f, 0.f, 0.f);
    float4 acc1 = make_float4(0.f, 0.f, 0.f, 0.f);

    for (int base = s; base < e; base += 32) {
        const int n = min(32, e - base);
        int2 cw = make_int2(0, 0);
        if (lane < n) cw = g_csr[base + lane];

        int j = 0;
        for (; j + 4 <= n; j += 4) {
            const int col0 = __shfl_sync(0xffffffffu, cw.x, j);
            const int w0i  = __shfl_sync(0xffffffffu, cw.y, j);
            const int col1 = __shfl_sync(0xffffffffu, cw.x, j + 1);
            const int w1i  = __shfl_sync(0xffffffffu, cw.y, j + 1);
            const int col2 = __shfl_sync(0xffffffffu, cw.x, j + 2);
            const int w2i  = __shfl_sync(0xffffffffu, cw.y, j + 2);
            const int col3 = __shfl_sync(0xffffffffu, cw.x, j + 3);
            const int w3i  = __shfl_sync(0xffffffffu, cw.y, j + 3);

            const uint2 p0 = ((const uint2*)(g_h + (size_t)col0 * 16))[lane];
            const uint2 p1 = ((const uint2*)(g_h + (size_t)col1 * 16))[lane];
            const uint2 p2 = ((const uint2*)(g_h + (size_t)col2 * 16))[lane];
            const uint2 p3 = ((const uint2*)(g_h + (size_t)col3 * 16))[lane];

            const float w0 = __int_as_float(w0i);
            const float w1 = __int_as_float(w1i);
            const float w2 = __int_as_float(w2i);
            const float w3 = __int_as_float(w3i);

            float2 a, b;
            a = __half22float2(*reinterpret_cast<const __half2*>(&p0.x));
            b = __half22float2(*reinterpret_cast<const __half2*>(&p0.y));
            acc0.x += w0 * a.x; acc0.y += w0 * a.y; acc0.z += w0 * b.x; acc0.w += w0 * b.y;
            a = __half22float2(*reinterpret_cast<const __half2*>(&p1.x));
            b = __half22float2(*reinterpret_cast<const __half2*>(&p1.y));
            acc1.x += w1 * a.x; acc1.y += w1 * a.y; acc1.z += w1 * b.x; acc1.w += w1 * b.y;
            a = __half22float2(*reinterpret_cast<const __half2*>(&p2.x));
            b = __half22float2(*reinterpret_cast<const __half2*>(&p2.y));
            acc0.x += w2 * a.x; acc0.y += w2 * a.y; acc0.z += w2 * b.x; acc0.w += w2 * b.y;
            a = __half22float2(*reinterpret_cast<const __half2*>(&p3.x));
            b = __half22float2(*reinterpret_cast<const __half2*>(&p3.y));
            acc1.x += w3 * a.x; acc1.y += w3 * a.y; acc1.z += w3 * b.x; acc1.w += w3 * b.y;
        }
        for (; j < n; j++) {
            const int col = __shfl_sync(0xffffffffu, cw.x, j);
            const int wi  = __shfl_sync(0xffffffffu, cw.y, j);
            const uint2 p = ((const uint2*)(g_h + (size_t)col * 16))[lane];
            const float wt = __int_as_float(wi);
            const float2 a = __half22float2(*reinterpret_cast<const __half2*>(&p.x));
            const float2 b = __half22float2(*reinterpret_cast<const __half2*>(&p.y));
            acc0.x += wt * a.x; acc0.y += wt * a.y; acc0.z += wt * b.x; acc0.w += wt * b.y;
        }
    }

    acc0.x += acc1.x; acc0.y += acc1.y; acc0.z += acc1.z; acc0.w += acc1.w;
    ((float4*)(out + (size_t)node * D))[lane] = acc0;
}

// ---------------------------------------------------------------------------
// Launch
// ---------------------------------------------------------------------------
extern "C" void kernel_launch(void* const* d_in, const int* in_sizes, int n_in,
                              void* d_out, int out_size) {
    const float* node_emb    = (const float*)d_in[0];
    const int*   edges       = (const int*)d_in[1];
    const float* edge_weight = (const float*)d_in[2];
    const float* W           = (const float*)d_in[3];
    float*       out         = (float*)d_out;

    const int n_nodes = in_sizes[0] / D;
    const int n_edges = in_sizes[1] / 2;
    const int n_chunks = (n_nodes + CHUNK - 1) / CHUNK;
    const int nq = n_edges >> 2;

    gemm_tc_kernel<<<(n_nodes + 127) / 128, 256, 0, 0>>>(node_emb, W, n_nodes);

    hist_kernel<<<(nq + 255) / 256, 256, 0, 0>>>(edges, n_edges, n_nodes);
    chunk_reduce_kernel<<<n_chunks, 256, 0, 0>>>(n_nodes);
    chunk_scan_kernel<<<1, MAX_CHUNKS, 0, 0>>>(n_chunks, n_nodes, n_edges);
    chunk_apply_kernel<<<n_chunks, CHUNK, 0, 0>>>(n_nodes);
    fill_kernel<<<(nq + 255) / 256, 256, 0, 0>>>(edges, edge_weight, n_edges, n_nodes);

    const int agg_blocks = (n_nodes * 32 + 255) / 256;
    agg_kernel<<<agg_blocks, 256, 0, 0>>>(out, n_nodes);
}